// round 16
// baseline (speedup 1.0000x reference)
#include <cuda_runtime.h>
#include <cuda_bf16.h>
#include <cstdint>
#include <cstddef>

// Problem constants
#define BB   512
#define KK   512
#define DIN  1024
#define DOUT 4096
#define C3K  1536          // 3*K
#define NROWS (BB*KK)      // 262144
#define NIT   (C3K/32)     // 48 k32-iterations

#define EMB_BLOCKS 1184
#define SPLIT_BLOCKS 512
#define NWARPS_EMB (EMB_BLOCKS * 8)    // 9472

// Scratch (static device globals — no allocation; zero-initialized at load,
// reset by the finalizing block each replay)
__device__ float g_stats[6];
__device__ float g_coef[6];            // scale[3], shift[3]
__device__ float g_rsum[3 * DOUT];     // per-channel rowsums of W
__device__ int   g_cnt;
__device__ __align__(16) __nv_bfloat16 g_Ah[BB * C3K];    // hi(raw y)
__device__ __align__(16) __nv_bfloat16 g_Al[BB * C3K];    // lo(raw y)
__device__ __align__(16) __nv_bfloat16 g_Bh[DOUT * C3K];  // hi(raw W)
__device__ __align__(16) __nv_bfloat16 g_Bl[DOUT * C3K];  // lo(raw W)

__device__ __forceinline__ void cpa16(uint32_t dst, const void* src) {
    asm volatile("cp.async.cg.shared.global [%0], [%1], 16;" :: "r"(dst), "l"(src));
}
#define CPA_COMMIT() asm volatile("cp.async.commit_group;" ::: "memory")
#define CPA_WAIT(n)  asm volatile("cp.async.wait_group %0;" :: "n"(n) : "memory")

// ---------------------------------------------------------------------------
// k_front (fused): blocks [0,1184): embed (cp.async row ring) + BN stats
// accumulation + last-embed-block coef finalize; blocks [1184,1696): raw-W
// bf16 split + per-channel rowsums.
// ---------------------------------------------------------------------------
__global__ __launch_bounds__(256, 2) void k_front(const float* __restrict__ x,
                                                  const float* __restrict__ Wemb,
                                                  const float* __restrict__ bemb,
                                                  const float* __restrict__ W,
                                                  const float* __restrict__ gamma,
                                                  const float* __restrict__ beta) {
    extern __shared__ __align__(16) float4 sx[];   // [8 warps][3 slots][256]
    const int tid = threadIdx.x;
    const int wid = tid >> 5, lane = tid & 31;

    if (blockIdx.x >= EMB_BLOCKS) {
        // ---- W split + rowsums: one warp per output row ----
        const int row = (blockIdx.x - EMB_BLOCKS) * 8 + wid;   // 0..4095
        const float4* wr = (const float4*)(W + (size_t)row * C3K);
        float rsum[3] = {0.f, 0.f, 0.f};
#pragma unroll
        for (int p = 0; p < 12; p++) {
            const int i = p * 32 + lane;
            const int o = i >> 7;
            float4 v = wr[i];
            rsum[o] += v.x + v.y + v.z + v.w;
            float a[4] = {v.x, v.y, v.z, v.w};
            __nv_bfloat16 h[4], l[4];
#pragma unroll
            for (int j = 0; j < 4; j++) {
                h[j] = __float2bfloat16_rn(a[j]);
                l[j] = __float2bfloat16_rn(a[j] - __bfloat162float(h[j]));
            }
            const size_t e = (size_t)row * C3K + i * 4;
            *(__nv_bfloat162*)&g_Bh[e]     = __nv_bfloat162(h[0], h[1]);
            *(__nv_bfloat162*)&g_Bh[e + 2] = __nv_bfloat162(h[2], h[3]);
            *(__nv_bfloat162*)&g_Bl[e]     = __nv_bfloat162(l[0], l[1]);
            *(__nv_bfloat162*)&g_Bl[e + 2] = __nv_bfloat162(l[2], l[3]);
        }
#pragma unroll
        for (int off = 16; off; off >>= 1)
#pragma unroll
            for (int o = 0; o < 3; o++)
                rsum[o] += __shfl_xor_sync(0xffffffffu, rsum[o], off);
        if (lane == 0) {
#pragma unroll
            for (int o = 0; o < 3; o++) g_rsum[o * DOUT + row] = rsum[o];
        }
        return;
    }

    // ---- embed path ----
    float4 w0[8], w1[8], w2[8];
    const float4* W4 = (const float4*)Wemb;
#pragma unroll
    for (int j = 0; j < 8; j++) {
        w0[j] = W4[      j * 32 + lane];
        w1[j] = W4[256 + j * 32 + lane];
        w2[j] = W4[512 + j * 32 + lane];
    }
    const float b0 = bemb[0], b1 = bemb[1], b2 = bemb[2];

    const int gw = blockIdx.x * 8 + wid;                  // 0..9471
    const int nr = (NROWS - 1 - gw) / NWARPS_EMB + 1;     // 27 or 28
    float4* ring = sx + (size_t)wid * 3 * 256;
    const uint32_t sb = (uint32_t)__cvta_generic_to_shared(ring);

    auto issue = [&](int i) {
        const char* src = (const char*)x
            + ((size_t)gw + (size_t)i * NWARPS_EMB) * 4096 + lane * 16;
        const uint32_t dst = sb + (uint32_t)(i % 3) * 4096 + lane * 16;
#pragma unroll
        for (int c = 0; c < 8; c++)
            cpa16(dst + c * 512, src + c * 512);
        CPA_COMMIT();
    };

    issue(0);
    if (nr > 1) issue(1);

    float ls[3] = {0.f, 0.f, 0.f};    // lane-0 stat accumulators
    float lq[3] = {0.f, 0.f, 0.f};

    for (int i = 0; i < nr; i++) {
        if (i + 1 < nr) CPA_WAIT(1);
        else CPA_WAIT(0);
        if (i + 2 < nr) issue(i + 2);

        const float4* xs = ring + (i % 3) * 256;
        float a0 = 0.f, a1 = 0.f, a2 = 0.f;
#pragma unroll
        for (int j = 0; j < 8; j++) {
            float4 xv = xs[j * 32 + lane];
            a0 += xv.x * w0[j].x + xv.y * w0[j].y + xv.z * w0[j].z + xv.w * w0[j].w;
            a1 += xv.x * w1[j].x + xv.y * w1[j].y + xv.z * w1[j].z + xv.w * w1[j].w;
            a2 += xv.x * w2[j].x + xv.y * w2[j].y + xv.z * w2[j].z + xv.w * w2[j].w;
        }
#pragma unroll
        for (int off = 16; off; off >>= 1) {
            a0 += __shfl_xor_sync(0xffffffffu, a0, off);
            a1 += __shfl_xor_sync(0xffffffffu, a1, off);
            a2 += __shfl_xor_sync(0xffffffffu, a2, off);
        }
        if (lane == 0) {
            const int row = gw + i * NWARPS_EMB;
            const int b = row >> 9, k = row & 511;
            const size_t base = (size_t)b * C3K + k;
            const float yv[3] = {a0 + b0, a1 + b1, a2 + b2};
#pragma unroll
            for (int o = 0; o < 3; o++) {
                __nv_bfloat16 h = __float2bfloat16_rn(yv[o]);
                __nv_bfloat16 l = __float2bfloat16_rn(yv[o] - __bfloat162float(h));
                g_Ah[base + o * 512] = h;
                g_Al[base + o * 512] = l;
                ls[o] += yv[o];
                lq[o] += yv[o] * yv[o];
            }
        }
    }

    // ---- block-level stats reduction + last-block finalize ----
    __shared__ float rs[6];
    __shared__ int is_last;
    if (tid < 6) rs[tid] = 0.f;
    __syncthreads();
    if (lane == 0) {
#pragma unroll
        for (int o = 0; o < 3; o++) {
            atomicAdd(&rs[o], ls[o]);
            atomicAdd(&rs[3 + o], lq[o]);
        }
    }
    __syncthreads();
    if (tid < 6) atomicAdd(&g_stats[tid], rs[tid]);
    if (tid == 0) {
        __threadfence();
        int old = atomicAdd(&g_cnt, 1);
        is_last = (old == EMB_BLOCKS - 1) ? 1 : 0;
    }
    __syncthreads();
    if (is_last && tid == 0) {
        __threadfence();
        const float n = (float)NROWS;
#pragma unroll
        for (int o = 0; o < 3; o++) {
            float sm = atomicAdd(&g_stats[o], 0.0f);
            float sq = atomicAdd(&g_stats[3 + o], 0.0f);
            float mean = sm / n;
            float var  = sq / n - mean * mean;
            float sc   = gamma[o] * rsqrtf(var + 1e-5f);
            g_coef[o]     = sc;
            g_coef[3 + o] = beta[o] - mean * sc;
            g_stats[o]     = 0.f;    // reset for next graph replay
            g_stats[3 + o] = 0.f;
        }
        g_cnt = 0;
    }
}
#define FRONT_SMEM (8 * 3 * 4096)    // 98304

// ---------------------------------------------------------------------------
// k_mma: raw-y @ raw-W with per-channel rescale at k boundaries (R13 design).
// CTA 64x128, grid (32,8), 2 CTAs/SM, 4-stage mbarrier cp.async ring.
// ---------------------------------------------------------------------------
#define LDSM_X4(r0, r1, r2, r3, a) \
    asm volatile("ldmatrix.sync.aligned.m8n8.x4.shared.b16 {%0,%1,%2,%3}, [%4];" \
                 : "=r"(r0), "=r"(r1), "=r"(r2), "=r"(r3) : "r"(a))

#define MMA_BF16(d, a, b0r, b1r) \
    asm volatile("mma.sync.aligned.m16n8k16.row.col.f32.bf16.bf16.f32 " \
                 "{%0,%1,%2,%3},{%4,%5,%6,%7},{%8,%9},{%0,%1,%2,%3};" \
                 : "+f"((d)[0]), "+f"((d)[1]), "+f"((d)[2]), "+f"((d)[3]) \
                 : "r"((a)[0]), "r"((a)[1]), "r"((a)[2]), "r"((a)[3]), \
                   "r"(b0r), "r"(b1r))

#define MBAR_INIT(a, cnt) \
    asm volatile("mbarrier.init.shared.b64 [%0], %1;" :: "r"(a), "r"(cnt) : "memory")
#define MBAR_ARRIVE(a) \
    asm volatile("mbarrier.arrive.shared.b64 _, [%0];" :: "r"(a) : "memory")
#define CPA_MBAR_ARRIVE(a) \
    asm volatile("cp.async.mbarrier.arrive.noinc.shared.b64 [%0];" :: "r"(a) : "memory")
#define MBAR_WAIT(a, ph) do {                                                  \
    uint32_t _d;                                                               \
    asm volatile("{\n\t.reg .pred p;\n\t"                                      \
        "mbarrier.try_wait.parity.acquire.cta.shared::cta.b64 p, [%1], %2;\n\t"\
        "selp.b32 %0,1,0,p;\n\t}" : "=r"(_d) : "r"(a), "r"((uint32_t)(ph)) : "memory"); \
    if (!_d) {                                                                 \
        asm volatile("{\n\t.reg .pred P1;\n"                                   \
            "WL_%=:\n\t"                                                       \
            "mbarrier.try_wait.parity.acquire.cta.shared::cta.b64 P1, [%0], %1, 0x989680;\n\t" \
            "@P1 bra.uni WD_%=;\n\t"                                           \
            "bra.uni WL_%=;\n"                                                 \
            "WD_%=:\n\t}" :: "r"(a), "r"((uint32_t)(ph)) : "memory");          \
    } } while (0)

__device__ __forceinline__ uint32_t tswz(int row, int c) {
    return (uint32_t)(row * 64 + ((c ^ ((row ^ (row >> 2)) & 3)) << 4));
}

#define TILE_A   4096
#define TILE_BB  8192
#define STAGE_B  (2 * TILE_A + 2 * TILE_BB)   // 24576
#define RING_B   (4 * STAGE_B)                // 98304
#define SMEM_B   (RING_B + 64)

__global__ __launch_bounds__(256, 2) void k_mma(float* __restrict__ out) {
    extern __shared__ __align__(128) char smem[];
    const uint32_t sbase = (uint32_t)__cvta_generic_to_shared(smem);
    const uint32_t fbar0 = sbase + RING_B;
    const uint32_t ebar0 = sbase + RING_B + 32;

    const int tid = threadIdx.x;
    const int wid = tid >> 5, lane = tid & 31;
    const int warp_m = wid & 1;
    const int warp_n = wid >> 1;
    const int bn = blockIdx.x;
    const int bm = blockIdx.y;

    if (tid == 0) {
#pragma unroll
        for (int s = 0; s < 4; s++) {
            MBAR_INIT(fbar0 + s * 8, 256);
            MBAR_INIT(ebar0 + s * 8, 8);
        }
    }
    __syncthreads();

    const float sc0 = g_coef[0], sc1 = g_coef[1], sc2 = g_coef[2];
    const float sh0 = g_coef[3], sh1 = g_coef[4], sh2 = g_coef[5];
    const float r01 = sc0 / sc1, r12 = sc1 / sc2;

    const int srow = tid >> 2, scn = tid & 3;
    const __nv_bfloat16* gA[2] = {
        g_Ah + (size_t)(bm * 64 + srow) * C3K + scn * 8,
        g_Al + (size_t)(bm * 64 + srow) * C3K + scn * 8};
    const __nv_bfloat16* gB[2] = {
        g_Bh + (size_t)(bn * 128 + srow) * C3K + scn * 8,
        g_Bl + (size_t)(bn * 128 + srow) * C3K + scn * 8};
    const uint32_t soffA  = tswz(srow, scn);
    const uint32_t soffB0 = tswz(srow, scn);
    const uint32_t soffB1 = tswz(srow + 64, scn);
    const size_t bstride64 = (size_t)64 * C3K;

    uint32_t offA[2][2], offB[2][2];
#pragma unroll
    for (int mf = 0; mf < 2; mf++)
#pragma unroll
        for (int j = 0; j < 2; j++)
            offA[mf][j] = tswz(warp_m * 32 + mf * 16 + (lane & 15),
                               2 * j + (lane >> 4));
#pragma unroll
    for (int ng = 0; ng < 2; ng++)
#pragma unroll
        for (int j = 0; j < 2; j++)
            offB[ng][j] = tswz(warp_n * 32 + ng * 16 + ((lane >> 4) << 3) + (lane & 7),
                               2 * j + ((lane >> 3) & 1));

    float acc[2][4][4];
#pragma unroll
    for (int mf = 0; mf < 2; mf++)
#pragma unroll
        for (int nf = 0; nf < 4; nf++)
#pragma unroll
            for (int r = 0; r < 4; r++) acc[mf][nf][r] = 0.f;

    auto produce = [&](int it2) {
        const int s2 = it2 & 3;
        const uint32_t pph = ((it2 >> 2) + 1) & 1;
        MBAR_WAIT(ebar0 + s2 * 8, pph);
        const uint32_t st = sbase + s2 * STAGE_B;
        const int koff = it2 * 32;
        cpa16(st + 0 * TILE_A + soffA, gA[0] + koff);
        cpa16(st + 1 * TILE_A + soffA, gA[1] + koff);
        const uint32_t bbase = st + 2 * TILE_A;
        cpa16(bbase + soffB0,           gB[0] + koff);
        cpa16(bbase + soffB1,           gB[0] + koff + bstride64);
        cpa16(bbase + TILE_BB + soffB0, gB[1] + koff);
        cpa16(bbase + TILE_BB + soffB1, gB[1] + koff + bstride64);
        CPA_MBAR_ARRIVE(fbar0 + s2 * 8);
    };

    produce(0); produce(1); produce(2);

    for (int it = 0; it < NIT; it++) {
        const int s = it & 3;
        const uint32_t cph = (it >> 2) & 1;
        MBAR_WAIT(fbar0 + s * 8, cph);
        if (it + 3 < NIT) produce(it + 3);

        const uint32_t stg = sbase + s * STAGE_B;
        const uint32_t bstg = stg + 2 * TILE_A;

        uint32_t ah[2][2][4], al[2][2][4], bh[2][2][4], bl[2][2][4];
#pragma unroll
        for (int j = 0; j < 2; j++) {
#pragma unroll
            for (int mf = 0; mf < 2; mf++) {
                LDSM_X4(ah[j][mf][0], ah[j][mf][1], ah[j][mf][2], ah[j][mf][3],
                        stg + 0 * TILE_A + offA[mf][j]);
                LDSM_X4(al[j][mf][0], al[j][mf][1], al[j][mf][2], al[j][mf][3],
                        stg + 1 * TILE_A + offA[mf][j]);
            }
#pragma unroll
            for (int ng = 0; ng < 2; ng++) {
                LDSM_X4(bh[j][ng][0], bh[j][ng][1], bh[j][ng][2], bh[j][ng][3],
                        bstg + offB[ng][j]);
                LDSM_X4(bl[j][ng][0], bl[j][ng][1], bl[j][ng][2], bl[j][ng][3],
                        bstg + TILE_BB + offB[ng][j]);
            }
        }
        if (lane == 0) MBAR_ARRIVE(ebar0 + s * 8);

#pragma unroll
        for (int j = 0; j < 2; j++) {
#pragma unroll
            for (int mf = 0; mf < 2; mf++) {
#pragma unroll
                for (int nf = 0; nf < 4; nf++) {
                    const int ng = nf >> 1, hb = (nf & 1) * 2;
                    MMA_BF16(acc[mf][nf], ah[j][mf], bh[j][ng][hb], bh[j][ng][hb + 1]);
                    MMA_BF16(acc[mf][nf], ah[j][mf], bl[j][ng][hb], bl[j][ng][hb + 1]);
                    MMA_BF16(acc[mf][nf], al[j][mf], bh[j][ng][hb], bh[j][ng][hb + 1]);
                }
            }
        }

        if (it == 15 || it == 31) {
            const float r = (it == 15) ? r01 : r12;
#pragma unroll
            for (int mf = 0; mf < 2; mf++)
#pragma unroll
                for (int nf = 0; nf < 4; nf++)
#pragma unroll
                    for (int q = 0; q < 4; q++) acc[mf][nf][q] *= r;
        }
    }

    const int mbase = bm * 64 + warp_m * 32 + (lane >> 2);
    const int nbase = bn * 128 + warp_n * 32 + 2 * (lane & 3);
#pragma unroll
    for (int mf = 0; mf < 2; mf++) {
#pragma unroll
        for (int nf = 0; nf < 4; nf++) {
            const int m = mbase + mf * 16;
            const int n = nbase + nf * 8;
            const float bz0 = sh0 * g_rsum[n] + sh1 * g_rsum[DOUT + n]
                            + sh2 * g_rsum[2 * DOUT + n];
            const float bz1 = sh0 * g_rsum[n + 1] + sh1 * g_rsum[DOUT + n + 1]
                            + sh2 * g_rsum[2 * DOUT + n + 1];
            *(float2*)(out + (size_t)m * DOUT + n) =
                make_float2(acc[mf][nf][0] * sc2 + bz0, acc[mf][nf][1] * sc2 + bz1);
            *(float2*)(out + (size_t)(m + 8) * DOUT + n) =
                make_float2(acc[mf][nf][2] * sc2 + bz0, acc[mf][nf][3] * sc2 + bz1);
        }
    }
}

// ---------------------------------------------------------------------------
// Launch
// ---------------------------------------------------------------------------
extern "C" void kernel_launch(void* const* d_in, const int* in_sizes, int n_in,
                              void* d_out, int out_size) {
    const float* x     = (const float*)d_in[0];
    const float* Wemb  = (const float*)d_in[1];
    const float* bemb  = (const float*)d_in[2];
    const float* gamma = (const float*)d_in[3];
    const float* beta  = (const float*)d_in[4];
    const float* Wfc2  = (const float*)d_in[5];
    float* out = (float*)d_out;

    static int smem_set = 0;
    if (!smem_set) {
        cudaFuncSetAttribute(k_mma, cudaFuncAttributeMaxDynamicSharedMemorySize, SMEM_B);
        cudaFuncSetAttribute(k_front, cudaFuncAttributeMaxDynamicSharedMemorySize, FRONT_SMEM);
        smem_set = 1;
    }

    k_front<<<EMB_BLOCKS + SPLIT_BLOCKS, 256, FRONT_SMEM>>>(x, Wemb, bemb, Wfc2, gamma, beta);
    k_mma<<<dim3(32, 8), 256, SMEM_B>>>(out);
}